// round 15
// baseline (speedup 1.0000x reference)
#include <cuda_runtime.h>
#include <cstdint>

#define BB 16
#define SS 4096
#define VV 1024
#define INV_SQRT_S 0.015625f   // 1/sqrt(4096)
#define NB 592                 // 148 SMs x 4 CTAs: exactly one resident wave

// Scratch (no allocations allowed)
__device__ float g_qp[2][BB * VV];   // q partials (v-halves)
__device__ float g_u[BB * VV];
__device__ float g_c[BB];
__device__ float g_y[BB * VV];
__device__ float g_A[BB];

// Device-wide sense-reversal barrier (generation-based: safe across graph replays)
__device__ unsigned g_barcnt = 0;
__device__ volatile unsigned g_bargen = 0;

__device__ __forceinline__ void gbar() {
    __syncthreads();
    if (threadIdx.x == 0) {
        __threadfence();
        unsigned gen = g_bargen;
        if (atomicAdd(&g_barcnt, 1u) == NB - 1u) {
            g_barcnt = 0;
            __threadfence();
            g_bargen = gen + 1u;
        } else {
            while (g_bargen == gen) __nanosleep(64);
        }
    }
    __syncthreads();
    __threadfence();
}

// Reduce acc[0..15] across 32 lanes in 16 SHFLs (vs 80 naive).
// Returns, on every lane, the full sum for b = (lane >> 1) & 15.
__device__ __forceinline__ float reduce16x32(float* acc, int lane) {
#pragma unroll
    for (int step = 0; step < 4; step++) {
        const int off = 16 >> step;    // 16,8,4,2
        const int half = 8 >> step;    // 8,4,2,1
#pragma unroll
        for (int i = 0; i < half; i++) {
            bool hi = (lane & off) != 0;
            float mine = hi ? acc[i + half] : acc[i];
            float theirs = hi ? acc[i] : acc[i + half];
            acc[i] = mine + __shfl_xor_sync(0xffffffffu, theirs, off);
        }
    }
    return acc[0] + __shfl_xor_sync(0xffffffffu, acc[0], 1);
}

// ---------------------------------------------------------------------------
// Single persistent kernel:
//   A: q partials (512 blocks: o x v-half; float4 staging, Wq read once)
//      + zeroing of g_u/g_y/g_A/out by blocks 512..591
//   B: u = q @ Wk (512 blocks, Wk read once); c[b] = q[b].bk (16 blocks)
//   C: fused main pass: contiguous 27-28-row blocks per warp, 2 rows/iter,
//      u in smem (268 MB single sequential-stream read)
//   D: out partials (512 blocks: o x v-half; float4 staging; Wv read once)
// ---------------------------------------------------------------------------
__global__ void __launch_bounds__(128, 4) fused_kernel(
        const float* __restrict__ pool, const float* __restrict__ X,
        const float* __restrict__ Wq, const float* __restrict__ bq,
        const float* __restrict__ Wk, const float* __restrict__ bk,
        const float* __restrict__ Wv, const float* __restrict__ bv,
        float* __restrict__ out) {
    const int warp = threadIdx.x >> 5, lane = threadIdx.x & 31;
    __shared__ float sh[BB * 256];   // 16 KB staging buffer, reused per phase
    __shared__ float shA;
    float4* const sh4 = (float4*)sh;

    // ---------- Phase A: q partial over v-half ----------
    if (blockIdx.x < 512) {
        const int vh = blockIdx.x & 1;                 // v-half: 0 or 1
        const int o = (blockIdx.x >> 1) * 4 + warp;    // 0..1023
        const int vbase = vh * 512;
        const float4* pool4 = (const float4*)pool;
        float acc[16];
#pragma unroll
        for (int b = 0; b < 16; b++) acc[b] = 0.f;

#pragma unroll
        for (int ch = 0; ch < 2; ch++) {
            __syncthreads();
#pragma unroll
            for (int k = 0; k < 8; k++) {
                int i = k * 128 + threadIdx.x;
                int b = i >> 6, v4 = i & 63;
                sh4[i] = pool4[b * 256 + (vbase >> 2) + ch * 64 + v4];
            }
            __syncthreads();
#pragma unroll
            for (int j = 0; j < 8; j++) {
                float w = Wq[(size_t)o * VV + vbase + ch * 256 + j * 32 + lane];
#pragma unroll
                for (int b = 0; b < 16; b++)
                    acc[b] = fmaf(w, sh[b * 256 + j * 32 + lane], acc[b]);
            }
        }
        float r = reduce16x32(acc, lane);
        if (!(lane & 1)) {
            int b = lane >> 1;
            float bqo = (vh == 0) ? bq[o] : 0.f;
            g_qp[vh][(size_t)b * VV + o] = r + bqo;
        }
    } else {
        for (int t = (blockIdx.x - 512) * 128 + threadIdx.x; t < BB * VV;
             t += 80 * 128) {
            g_u[t] = 0.f; g_y[t] = 0.f; out[t] = 0.f;
        }
        if (blockIdx.x == 512 && threadIdx.x < BB) g_A[threadIdx.x] = 0.f;
    }
    gbar();

    // ---------- Phase B: u[b][v] = sum_o q[b][o]*Wk[o][v];  c[b] = q[b].bk ----------
    if (blockIdx.x < 512) {
        const int o0 = (blockIdx.x >> 3) * 16;
        const int v = (blockIdx.x & 7) * 128 + threadIdx.x;

#pragma unroll
        for (int k = 0; k < 2; k++) {
            int i = k * 128 + threadIdx.x;
            int b = i >> 4, oo = i & 15;
            size_t idx = (size_t)b * VV + o0 + oo;
            sh[i] = g_qp[0][idx] + g_qp[1][idx];
        }
        __syncthreads();

        float acc[16];
#pragma unroll
        for (int b = 0; b < 16; b++) acc[b] = 0.f;
#pragma unroll
        for (int oo = 0; oo < 16; oo++) {
            float w = Wk[(size_t)(o0 + oo) * VV + v];
#pragma unroll
            for (int b = 0; b < 16; b++)
                acc[b] = fmaf(sh[b * 16 + oo], w, acc[b]);
        }
#pragma unroll
        for (int b = 0; b < 16; b++)
            atomicAdd(&g_u[(size_t)b * VV + v], acc[b]);
    } else if (blockIdx.x < 528) {
        const int b = blockIdx.x - 512;
        float s = 0.f;
#pragma unroll
        for (int j = 0; j < 8; j++) {
            int o = j * 128 + threadIdx.x;
            size_t idx = (size_t)b * VV + o;
            s = fmaf(g_qp[0][idx] + g_qp[1][idx], bk[o], s);
        }
#pragma unroll
        for (int off = 16; off; off >>= 1) s += __shfl_xor_sync(0xffffffffu, s, off);
        if (lane == 0) sh[warp] = s;
        __syncthreads();
        if (threadIdx.x == 0) g_c[b] = sh[0] + sh[1] + sh[2] + sh[3];
    }
    gbar();

    // ---------- Phase C: contiguous streams, 2 rows per iteration ----------
    {
        const int b = blockIdx.x & 15;
        const int wg = (blockIdx.x >> 4) * 4 + warp;   // 0..147
        // contiguous row range: first 100 warps get 28 rows, rest 27
        const int cnt = 27 + (wg < 100 ? 1 : 0);
        const int r0 = wg * 27 + (wg < 100 ? wg : 100);

        float* const shU = sh;          // u[b] : sh[0..1023]
        float* const ys = sh + 1024;    // block y accum : sh[1024..2047]
        for (int i = threadIdx.x; i < VV; i += 128) {
            shU[i] = g_u[(size_t)b * VV + i];
            ys[i] = 0.f;
        }
        if (threadIdx.x == 0) shA = 0.f;
        __syncthreads();

        const float cb = g_c[b];
        const float4* shU4 = (const float4*)shU;
        const float4* Xb = (const float4*)(X + (size_t)b * SS * VV);

        float yacc[32];
#pragma unroll
        for (int i = 0; i < 32; i++) yacc[i] = 0.f;
        float Aacc = 0.f;

        int row = r0;
        const int rend = r0 + cnt;
        for (; row + 1 < rend; row += 2) {
            const float4* xr1 = Xb + (size_t)row * 256;
            const float4* xr2 = xr1 + 256;
            float4 xa[8], xb4[8];
#pragma unroll
            for (int j = 0; j < 8; j++) xa[j] = xr1[j * 32 + lane];
#pragma unroll
            for (int j = 0; j < 8; j++) xb4[j] = xr2[j * 32 + lane];

            float s1a = 0.f, s1b = 0.f, s2a = 0.f, s2b = 0.f;
#pragma unroll
            for (int j = 0; j < 8; j++) {
                float4 u4 = shU4[j * 32 + lane];
                float t1 = fmaf(xa[j].w, u4.w, fmaf(xa[j].z, u4.z,
                           fmaf(xa[j].y, u4.y, xa[j].x * u4.x)));
                float t2 = fmaf(xb4[j].w, u4.w, fmaf(xb4[j].z, u4.z,
                           fmaf(xb4[j].y, u4.y, xb4[j].x * u4.x)));
                if (j & 1) { s1b += t1; s2b += t2; }
                else       { s1a += t1; s2a += t2; }
            }
            float d1 = s1a + s1b, d2 = s2a + s2b;
#pragma unroll
            for (int off = 16; off; off >>= 1) {
                d1 += __shfl_xor_sync(0xffffffffu, d1, off);
                d2 += __shfl_xor_sync(0xffffffffu, d2, off);
            }
            const float a1 = (d1 + cb) * INV_SQRT_S;
            const float a2 = (d2 + cb) * INV_SQRT_S;
            Aacc += a1 + a2;
#pragma unroll
            for (int j = 0; j < 8; j++) {
                yacc[j * 4 + 0] = fmaf(a1, xa[j].x, fmaf(a2, xb4[j].x, yacc[j * 4 + 0]));
                yacc[j * 4 + 1] = fmaf(a1, xa[j].y, fmaf(a2, xb4[j].y, yacc[j * 4 + 1]));
                yacc[j * 4 + 2] = fmaf(a1, xa[j].z, fmaf(a2, xb4[j].z, yacc[j * 4 + 2]));
                yacc[j * 4 + 3] = fmaf(a1, xa[j].w, fmaf(a2, xb4[j].w, yacc[j * 4 + 3]));
            }
        }
        if (row < rend) {   // odd tail row
            const float4* xr = Xb + (size_t)row * 256;
            float4 xa[8];
#pragma unroll
            for (int j = 0; j < 8; j++) xa[j] = xr[j * 32 + lane];
            float s1a = 0.f, s1b = 0.f;
#pragma unroll
            for (int j = 0; j < 8; j++) {
                float4 u4 = shU4[j * 32 + lane];
                float t = fmaf(xa[j].w, u4.w, fmaf(xa[j].z, u4.z,
                          fmaf(xa[j].y, u4.y, xa[j].x * u4.x)));
                if (j & 1) s1b += t; else s1a += t;
            }
            float d = s1a + s1b;
#pragma unroll
            for (int off = 16; off; off >>= 1) d += __shfl_xor_sync(0xffffffffu, d, off);
            const float a = (d + cb) * INV_SQRT_S;
            Aacc += a;
#pragma unroll
            for (int j = 0; j < 8; j++) {
                yacc[j * 4 + 0] = fmaf(a, xa[j].x, yacc[j * 4 + 0]);
                yacc[j * 4 + 1] = fmaf(a, xa[j].y, yacc[j * 4 + 1]);
                yacc[j * 4 + 2] = fmaf(a, xa[j].z, yacc[j * 4 + 2]);
                yacc[j * 4 + 3] = fmaf(a, xa[j].w, yacc[j * 4 + 3]);
            }
        }

        __syncthreads();
#pragma unroll
        for (int j = 0; j < 8; j++) {
            int col = j * 128 + lane * 4;
            atomicAdd(&ys[col + 0], yacc[j * 4 + 0]);
            atomicAdd(&ys[col + 1], yacc[j * 4 + 1]);
            atomicAdd(&ys[col + 2], yacc[j * 4 + 2]);
            atomicAdd(&ys[col + 3], yacc[j * 4 + 3]);
        }
        if (lane == 0) atomicAdd(&shA, Aacc);
        __syncthreads();
        for (int i = threadIdx.x; i < VV; i += 128)
            atomicAdd(&g_y[(size_t)b * VV + i], ys[i]);
        if (threadIdx.x == 0) atomicAdd(&g_A[b], shA);
    }
    gbar();

    // ---------- Phase D: out partial over v-half ----------
    if (blockIdx.x < 512) {
        const int vh = blockIdx.x & 1;
        const int o = (blockIdx.x >> 1) * 4 + warp;
        const int vbase = vh * 512;
        const float4* y4 = (const float4*)g_y;
        float acc[16];
#pragma unroll
        for (int b = 0; b < 16; b++) acc[b] = 0.f;

#pragma unroll
        for (int ch = 0; ch < 2; ch++) {
            __syncthreads();
#pragma unroll
            for (int k = 0; k < 8; k++) {
                int i = k * 128 + threadIdx.x;
                int b = i >> 6, v4 = i & 63;
                sh4[i] = y4[b * 256 + (vbase >> 2) + ch * 64 + v4];
            }
            __syncthreads();
#pragma unroll
            for (int j = 0; j < 8; j++) {
                float w = Wv[(size_t)o * VV + vbase + ch * 256 + j * 32 + lane];
#pragma unroll
                for (int b = 0; b < 16; b++)
                    acc[b] = fmaf(w, sh[b * 256 + j * 32 + lane], acc[b]);
            }
        }
        float r = reduce16x32(acc, lane);
        if (!(lane & 1)) {
            int b = lane >> 1;
            float r2 = r + ((vh == 0) ? g_A[b] * bv[o] : 0.f);
            atomicAdd(&out[(size_t)b * VV + o], r2);
        }
    }
}

// ---------------------------------------------------------------------------
extern "C" void kernel_launch(void* const* d_in, const int* in_sizes, int n_in,
                              void* d_out, int out_size) {
    const float* pool = (const float*)d_in[0];
    const float* bert = (const float*)d_in[1];
    const float* Wq   = (const float*)d_in[2];
    const float* bq   = (const float*)d_in[3];
    const float* Wk   = (const float*)d_in[4];
    const float* bk   = (const float*)d_in[5];
    const float* Wv   = (const float*)d_in[6];
    const float* bv   = (const float*)d_in[7];
    float* out = (float*)d_out;

    fused_kernel<<<NB, 128>>>(pool, bert, Wq, bq, Wk, bk, Wv, bv, out);
}

// round 16
// speedup vs baseline: 1.1235x; 1.1235x over previous
#include <cuda_runtime.h>
#include <cstdint>

#define BB 16
#define SS 4096
#define VV 1024
#define INV_SQRT_S 0.015625f   // 1/sqrt(4096)
#define NB 592                 // 148 SMs x 4 CTAs: exactly one resident wave

// Scratch (no allocations allowed)
__device__ float g_qp[2][BB * VV];   // q partials (v-halves)
__device__ float g_u[BB * VV];
__device__ float g_c[BB];
__device__ float g_y[BB * VV];
__device__ float g_A[BB];

// Device-wide sense-reversal barrier (generation-based: safe across graph replays)
__device__ unsigned g_barcnt = 0;
__device__ volatile unsigned g_bargen = 0;

__device__ __forceinline__ void gbar() {
    __syncthreads();
    if (threadIdx.x == 0) {
        __threadfence();
        unsigned gen = g_bargen;
        if (atomicAdd(&g_barcnt, 1u) == NB - 1u) {
            g_barcnt = 0;
            __threadfence();
            g_bargen = gen + 1u;
        } else {
            while (g_bargen == gen) __nanosleep(64);
        }
    }
    __syncthreads();
    __threadfence();
}

// Reduce acc[0..15] across 32 lanes in 16 SHFLs (vs 80 naive).
// Returns, on every lane, the full sum for b = (lane >> 1) & 15.
__device__ __forceinline__ float reduce16x32(float* acc, int lane) {
#pragma unroll
    for (int step = 0; step < 4; step++) {
        const int off = 16 >> step;    // 16,8,4,2
        const int half = 8 >> step;    // 8,4,2,1
#pragma unroll
        for (int i = 0; i < half; i++) {
            bool hi = (lane & off) != 0;
            float mine = hi ? acc[i + half] : acc[i];
            float theirs = hi ? acc[i] : acc[i + half];
            acc[i] = mine + __shfl_xor_sync(0xffffffffu, theirs, off);
        }
    }
    return acc[0] + __shfl_xor_sync(0xffffffffu, acc[0], 1);
}

// ---------------------------------------------------------------------------
// Single persistent kernel (R14 structure — best measured config):
//   A: q partials (512 blocks: o x v-half; float4 staging, Wq read once)
//      + zeroing of g_u/g_y/g_A/out by blocks 512..591
//   B: u = q @ Wk (512 blocks, Wk read once); c[b] = q[b].bk (16 blocks)
//   C: fused main pass over bert_output, interleaved rows (row += 148),
//      X read via __ldcs (streaming, read-once)
//   D: out partials (512 blocks: o x v-half; float4 staging; Wv read once)
// ---------------------------------------------------------------------------
__global__ void __launch_bounds__(128, 4) fused_kernel(
        const float* __restrict__ pool, const float* __restrict__ X,
        const float* __restrict__ Wq, const float* __restrict__ bq,
        const float* __restrict__ Wk, const float* __restrict__ bk,
        const float* __restrict__ Wv, const float* __restrict__ bv,
        float* __restrict__ out) {
    const int warp = threadIdx.x >> 5, lane = threadIdx.x & 31;
    __shared__ float sh[BB * 256];   // 16 KB staging buffer, reused per phase
    __shared__ float shA;
    float4* const sh4 = (float4*)sh;

    // ---------- Phase A: q partial over v-half ----------
    if (blockIdx.x < 512) {
        const int vh = blockIdx.x & 1;                 // v-half: 0 or 1
        const int o = (blockIdx.x >> 1) * 4 + warp;    // 0..1023
        const int vbase = vh * 512;
        const float4* pool4 = (const float4*)pool;
        float acc[16];
#pragma unroll
        for (int b = 0; b < 16; b++) acc[b] = 0.f;

#pragma unroll
        for (int ch = 0; ch < 2; ch++) {
            __syncthreads();
            // vectorized staging: 1024 float4s, 8 per thread, MLP 8
#pragma unroll
            for (int k = 0; k < 8; k++) {
                int i = k * 128 + threadIdx.x;
                int b = i >> 6, v4 = i & 63;
                sh4[i] = pool4[b * 256 + (vbase >> 2) + ch * 64 + v4];
            }
            __syncthreads();
#pragma unroll
            for (int j = 0; j < 8; j++) {
                float w = Wq[(size_t)o * VV + vbase + ch * 256 + j * 32 + lane];
#pragma unroll
                for (int b = 0; b < 16; b++)
                    acc[b] = fmaf(w, sh[b * 256 + j * 32 + lane], acc[b]);
            }
        }
        float r = reduce16x32(acc, lane);
        if (!(lane & 1)) {
            int b = lane >> 1;
            float bqo = (vh == 0) ? bq[o] : 0.f;
            g_qp[vh][(size_t)b * VV + o] = r + bqo;
        }
    } else {
        // blocks 512..591 zero accumulators and the output buffer
        for (int t = (blockIdx.x - 512) * 128 + threadIdx.x; t < BB * VV;
             t += 80 * 128) {
            g_u[t] = 0.f; g_y[t] = 0.f; out[t] = 0.f;
        }
        if (blockIdx.x == 512 && threadIdx.x < BB) g_A[threadIdx.x] = 0.f;
    }
    gbar();

    // ---------- Phase B: u[b][v] = sum_o q[b][o]*Wk[o][v];  c[b] = q[b].bk ----------
    if (blockIdx.x < 512) {
        const int o0 = (blockIdx.x >> 3) * 16;
        const int v = (blockIdx.x & 7) * 128 + threadIdx.x;

        // q chunk [16 b][16 o], q = sum of the two v-half partials
#pragma unroll
        for (int k = 0; k < 2; k++) {
            int i = k * 128 + threadIdx.x;
            int b = i >> 4, oo = i & 15;
            size_t idx = (size_t)b * VV + o0 + oo;
            sh[i] = g_qp[0][idx] + g_qp[1][idx];
        }
        __syncthreads();

        float acc[16];
#pragma unroll
        for (int b = 0; b < 16; b++) acc[b] = 0.f;
#pragma unroll
        for (int oo = 0; oo < 16; oo++) {
            float w = Wk[(size_t)(o0 + oo) * VV + v];
#pragma unroll
            for (int b = 0; b < 16; b++)
                acc[b] = fmaf(sh[b * 16 + oo], w, acc[b]);
        }
#pragma unroll
        for (int b = 0; b < 16; b++)
            atomicAdd(&g_u[(size_t)b * VV + v], acc[b]);
    } else if (blockIdx.x < 528) {
        // c[b] = dot(q[b], bk): one block per b, exact write (no atomics)
        const int b = blockIdx.x - 512;
        float s = 0.f;
#pragma unroll
        for (int j = 0; j < 8; j++) {
            int o = j * 128 + threadIdx.x;
            size_t idx = (size_t)b * VV + o;
            s = fmaf(g_qp[0][idx] + g_qp[1][idx], bk[o], s);
        }
#pragma unroll
        for (int off = 16; off; off >>= 1) s += __shfl_xor_sync(0xffffffffu, s, off);
        if (lane == 0) sh[warp] = s;
        __syncthreads();
        if (threadIdx.x == 0) g_c[b] = sh[0] + sh[1] + sh[2] + sh[3];
    }
    gbar();

    // ---------- Phase C: fused main pass over bert_output (R10/R14 config) ----------
    {
        const int b = blockIdx.x & 15;
        const int grp = blockIdx.x >> 4;          // 0..36
        const int wg = grp * 4 + warp;            // 0..147

        float4 u4[8];
        const float4* ub = (const float4*)(g_u + (size_t)b * VV);
#pragma unroll
        for (int j = 0; j < 8; j++) u4[j] = ub[j * 32 + lane];
        const float cb = g_c[b];

        float yacc[32];
#pragma unroll
        for (int i = 0; i < 32; i++) yacc[i] = 0.f;
        float Aacc = 0.f;

        const float4* Xb = (const float4*)(X + (size_t)b * SS * VV);
        for (int row = wg; row < SS; row += 148) {
            const float4* xr = Xb + (size_t)row * (VV / 4);
            float4 x4[8];
#pragma unroll
            for (int j = 0; j < 8; j++) x4[j] = __ldcs(&xr[j * 32 + lane]);

            float p[8];
#pragma unroll
            for (int j = 0; j < 8; j++)
                p[j] = fmaf(x4[j].w, u4[j].w,
                       fmaf(x4[j].z, u4[j].z,
                       fmaf(x4[j].y, u4[j].y, x4[j].x * u4[j].x)));
            float d = ((p[0] + p[1]) + (p[2] + p[3])) + ((p[4] + p[5]) + (p[6] + p[7]));
#pragma unroll
            for (int off = 16; off; off >>= 1) d += __shfl_xor_sync(0xffffffffu, d, off);

            const float a = (d + cb) * INV_SQRT_S;
            Aacc += a;
#pragma unroll
            for (int j = 0; j < 8; j++) {
                yacc[j * 4 + 0] = fmaf(a, x4[j].x, yacc[j * 4 + 0]);
                yacc[j * 4 + 1] = fmaf(a, x4[j].y, yacc[j * 4 + 1]);
                yacc[j * 4 + 2] = fmaf(a, x4[j].z, yacc[j * 4 + 2]);
                yacc[j * 4 + 3] = fmaf(a, x4[j].w, yacc[j * 4 + 3]);
            }
        }

        for (int i = threadIdx.x; i < VV; i += 128) sh[i] = 0.f;
        if (threadIdx.x == 0) shA = 0.f;
        __syncthreads();
#pragma unroll
        for (int j = 0; j < 8; j++) {
            int col = j * 128 + lane * 4;
            atomicAdd(&sh[col + 0], yacc[j * 4 + 0]);
            atomicAdd(&sh[col + 1], yacc[j * 4 + 1]);
            atomicAdd(&sh[col + 2], yacc[j * 4 + 2]);
            atomicAdd(&sh[col + 3], yacc[j * 4 + 3]);
        }
        if (lane == 0) atomicAdd(&shA, Aacc);
        __syncthreads();
        for (int i = threadIdx.x; i < VV; i += 128)
            atomicAdd(&g_y[(size_t)b * VV + i], sh[i]);
        if (threadIdx.x == 0) atomicAdd(&g_A[b], shA);
    }
    gbar();

    // ---------- Phase D: out partial over v-half ----------
    if (blockIdx.x < 512) {
        const int vh = blockIdx.x & 1;
        const int o = (blockIdx.x >> 1) * 4 + warp;
        const int vbase = vh * 512;
        const float4* y4 = (const float4*)g_y;
        float acc[16];
#pragma unroll
        for (int b = 0; b < 16; b++) acc[b] = 0.f;

#pragma unroll
        for (int ch = 0; ch < 2; ch++) {
            __syncthreads();
#pragma unroll
            for (int k = 0; k < 8; k++) {
                int i = k * 128 + threadIdx.x;
                int b = i >> 6, v4 = i & 63;
                sh4[i] = y4[b * 256 + (vbase >> 2) + ch * 64 + v4];
            }
            __syncthreads();
#pragma unroll
            for (int j = 0; j < 8; j++) {
                float w = Wv[(size_t)o * VV + vbase + ch * 256 + j * 32 + lane];
#pragma unroll
                for (int b = 0; b < 16; b++)
                    acc[b] = fmaf(w, sh[b * 256 + j * 32 + lane], acc[b]);
            }
        }
        float r = reduce16x32(acc, lane);
        if (!(lane & 1)) {
            int b = lane >> 1;
            float r2 = r + ((vh == 0) ? g_A[b] * bv[o] : 0.f);
            atomicAdd(&out[(size_t)b * VV + o], r2);
        }
    }
}

// ---------------------------------------------------------------------------
extern "C" void kernel_launch(void* const* d_in, const int* in_sizes, int n_in,
                              void* d_out, int out_size) {
    const float* pool = (const float*)d_in[0];
    const float* bert = (const float*)d_in[1];
    const float* Wq   = (const float*)d_in[2];
    const float* bq   = (const float*)d_in[3];
    const float* Wk   = (const float*)d_in[4];
    const float* bk   = (const float*)d_in[5];
    const float* Wv   = (const float*)d_in[6];
    const float* bv   = (const float*)d_in[7];
    float* out = (float*)d_out;

    fused_kernel<<<NB, 128>>>(pool, bert, Wq, bq, Wk, bk, Wv, bv, out);
}